// round 2
// baseline (speedup 1.0000x reference)
#include <cuda_runtime.h>
#include <cuda_bf16.h>
#include <cstddef>

#define N_NODES 100000
#define IN_DIM  256
#define OUT_DIM 128
#define N_EDGES 3200000

// Scratch for h = X @ W  (51.2 MB). __device__ global per allocation rules.
__device__ float g_h[(size_t)N_NODES * OUT_DIM];

// ---------------------------------------------------------------------------
// Kernel 1: out[n][o] = b[o]  (bias epilogue pre-seeded; scatter adds on top)
// ---------------------------------------------------------------------------
__global__ void init_bias_kernel(float* __restrict__ out, const float* __restrict__ b) {
    int i = blockIdx.x * blockDim.x + threadIdx.x;           // float4 index
    const int total4 = (N_NODES * OUT_DIM) / 4;              // 3.2M
    if (i >= total4) return;
    float4 bv = reinterpret_cast<const float4*>(b)[i & 31];  // OUT_DIM/4 = 32
    reinterpret_cast<float4*>(out)[i] = bv;
}

// ---------------------------------------------------------------------------
// Kernel 2: g_h = X @ W   fp32 SIMT GEMM
// Tile: BM=64 rows x 128 cols (full N), BK=32. 256 threads, each 8x4 outputs.
// smem: xs 8KB + ws 16KB = 24KB static.
// ---------------------------------------------------------------------------
#define BM 64
#define BK 32

__global__ __launch_bounds__(256) void gemm_kernel(const float* __restrict__ X,
                                                   const float* __restrict__ W,
                                                   float* __restrict__ H) {
    __shared__ float xs[BM * BK];        // [row][k]
    __shared__ float ws[BK * OUT_DIM];   // [k][col]

    const int tid = threadIdx.x;
    const int tx  = tid & 31;            // col group: cols 4*tx .. 4*tx+3
    const int ty  = tid >> 5;            // row group: rows ty*8 .. ty*8+7
    const int row0 = blockIdx.x * BM;

    float acc[8][4];
#pragma unroll
    for (int i = 0; i < 8; i++)
#pragma unroll
        for (int j = 0; j < 4; j++) acc[i][j] = 0.f;

    for (int k0 = 0; k0 < IN_DIM; k0 += BK) {
        // load xs: 64x32 floats = 512 float4, 2 per thread
#pragma unroll
        for (int l = 0; l < 2; l++) {
            int f = tid + l * 256;
            int r  = f >> 3;             // 8 float4 per row (BK=32)
            int kc = (f & 7) << 2;
            int grow = row0 + r;
            float4 v = make_float4(0.f, 0.f, 0.f, 0.f);
            if (grow < N_NODES)
                v = *reinterpret_cast<const float4*>(X + (size_t)grow * IN_DIM + k0 + kc);
            *reinterpret_cast<float4*>(xs + r * BK + kc) = v;
        }
        // load ws: 32x128 floats = 1024 float4, 4 per thread
#pragma unroll
        for (int l = 0; l < 4; l++) {
            int f = tid + l * 256;
            int kk = f >> 5;             // 32 float4 per k-row
            int c  = (f & 31) << 2;
            *reinterpret_cast<float4*>(ws + kk * OUT_DIM + c) =
                *reinterpret_cast<const float4*>(W + (size_t)(k0 + kk) * OUT_DIM + c);
        }
        __syncthreads();

#pragma unroll
        for (int k = 0; k < BK; k++) {
            float4 wv = *reinterpret_cast<const float4*>(ws + k * OUT_DIM + (tx << 2));
#pragma unroll
            for (int i = 0; i < 8; i++) {
                float xv = xs[(ty * 8 + i) * BK + k];
                acc[i][0] += xv * wv.x;
                acc[i][1] += xv * wv.y;
                acc[i][2] += xv * wv.z;
                acc[i][3] += xv * wv.w;
            }
        }
        __syncthreads();
    }

#pragma unroll
    for (int i = 0; i < 8; i++) {
        int row = row0 + ty * 8 + i;
        if (row < N_NODES) {
            float4 v = make_float4(acc[i][0], acc[i][1], acc[i][2], acc[i][3]);
            *reinterpret_cast<float4*>(H + (size_t)row * OUT_DIM + (tx << 2)) = v;
        }
    }
}

// ---------------------------------------------------------------------------
// Kernel 3: scatter-aggregate. One warp per edge.
// lane l handles cols 4l..4l+3: out[dst] += val * h[src]
// ---------------------------------------------------------------------------
__global__ __launch_bounds__(256) void scatter_kernel(const int* __restrict__ src,
                                                      const int* __restrict__ dst,
                                                      const float* __restrict__ vals,
                                                      const float* __restrict__ H,
                                                      float* __restrict__ out) {
    int e = blockIdx.x * (blockDim.x >> 5) + (threadIdx.x >> 5);
    if (e >= N_EDGES) return;
    int lane = threadIdx.x & 31;

    int   s = __ldg(src + e);
    int   d = __ldg(dst + e);
    float v = __ldg(vals + e);

    float4 hv = *reinterpret_cast<const float4*>(H + (size_t)s * OUT_DIM + (lane << 2));
    float* op = out + (size_t)d * OUT_DIM + (lane << 2);
    atomicAdd(op + 0, v * hv.x);
    atomicAdd(op + 1, v * hv.y);
    atomicAdd(op + 2, v * hv.z);
    atomicAdd(op + 3, v * hv.w);
}

// ---------------------------------------------------------------------------
extern "C" void kernel_launch(void* const* d_in, const int* in_sizes, int n_in,
                              void* d_out, int out_size) {
    const float* X    = (const float*)d_in[0];   // [N_NODES, IN_DIM]
    const int*   esrc = (const int*)  d_in[1];   // [N_EDGES]
    const int*   edst = (const int*)  d_in[2];   // [N_EDGES]
    const float* evls = (const float*)d_in[3];   // [N_EDGES]
    const float* W    = (const float*)d_in[4];   // [IN_DIM, OUT_DIM]
    const float* b    = (const float*)d_in[5];   // [OUT_DIM]
    float* out = (float*)d_out;                  // [N_NODES, OUT_DIM]

    float* H = nullptr;
    cudaGetSymbolAddress((void**)&H, g_h);

    // 1) out = bias (broadcast)
    {
        int total4 = (N_NODES * OUT_DIM) / 4;
        int threads = 256;
        int blocks = (total4 + threads - 1) / threads;
        init_bias_kernel<<<blocks, threads>>>(out, b);
    }

    // 2) H = X @ W
    {
        int blocks = (N_NODES + BM - 1) / BM;    // 1563
        gemm_kernel<<<blocks, 256>>>(X, W, H);
    }

    // 3) out[dst] += val * H[src]   (one warp per edge)
    {
        int edges_per_block = 256 / 32;          // 8
        int blocks = (N_EDGES + edges_per_block - 1) / edges_per_block;
        scatter_kernel<<<blocks, 256>>>(esrc, edst, evls, H, out);
    }
}

// round 3
// speedup vs baseline: 2.3592x; 2.3592x over previous
#include <cuda_runtime.h>
#include <cuda_bf16.h>
#include <cstddef>

#define N_NODES 100000
#define IN_DIM  256
#define OUT_DIM 128
#define N_EDGES 3200000

// ---------------------------------------------------------------------------
// Device scratch (static; no allocation allowed)
// ---------------------------------------------------------------------------
__device__ float g_h[(size_t)N_NODES * OUT_DIM];     // 51.2 MB  H = X@W
__device__ int   g_deg[N_NODES];                     // histogram of dst
__device__ int   g_off[N_NODES + 1];                 // CSR row offsets (by dst)
__device__ int   g_cur[N_NODES];                     // scatter cursors
__device__ int2  g_edges[N_EDGES];                   // binned {src, val-bits}

// ---------------------------------------------------------------------------
// Kernel A: histogram of edge destinations
// ---------------------------------------------------------------------------
__global__ __launch_bounds__(256) void hist_kernel(const int* __restrict__ dst) {
    int i = blockIdx.x * blockDim.x + threadIdx.x;
    if (i < N_EDGES) atomicAdd(&g_deg[__ldg(dst + i)], 1);
}

// ---------------------------------------------------------------------------
// Kernel B: exclusive prefix scan over g_deg -> g_off (single block)
// ---------------------------------------------------------------------------
#define SCAN_THREADS 1024
#define SCAN_ITEMS   98   // 1024*98 = 100352 >= N_NODES

__global__ __launch_bounds__(SCAN_THREADS) void scan_kernel() {
    __shared__ int sums[SCAN_THREADS];
    const int t = threadIdx.x;
    const int base = t * SCAN_ITEMS;

    // pass 1: per-thread chunk total
    int s = 0;
    for (int i = 0; i < SCAN_ITEMS; i++) {
        int idx = base + i;
        s += (idx < N_NODES) ? g_deg[idx] : 0;
    }
    sums[t] = s;
    __syncthreads();

    // inclusive Hillis-Steele over 1024 thread totals
    for (int ofs = 1; ofs < SCAN_THREADS; ofs <<= 1) {
        int v = (t >= ofs) ? sums[t - ofs] : 0;
        __syncthreads();
        sums[t] += v;
        __syncthreads();
    }
    int prefix = (t == 0) ? 0 : sums[t - 1];

    // pass 2: re-read chunk (L1/L2 hot), emit exclusive offsets
    int run = prefix;
    for (int i = 0; i < SCAN_ITEMS; i++) {
        int idx = base + i;
        if (idx < N_NODES) {
            g_off[idx] = run;
            run += g_deg[idx];
        }
    }
    if (t == SCAN_THREADS - 1) g_off[N_NODES] = sums[SCAN_THREADS - 1];
}

// ---------------------------------------------------------------------------
// Kernel C: scatter edges into dst-sorted bins
// ---------------------------------------------------------------------------
__global__ __launch_bounds__(256) void bin_kernel(const int* __restrict__ src,
                                                  const int* __restrict__ dst,
                                                  const float* __restrict__ vals) {
    int i = blockIdx.x * blockDim.x + threadIdx.x;
    if (i >= N_EDGES) return;
    int d = __ldg(dst + i);
    int pos = g_off[d] + atomicAdd(&g_cur[d], 1);
    g_edges[pos] = make_int2(__ldg(src + i), __float_as_int(__ldg(vals + i)));
}

// ---------------------------------------------------------------------------
// Kernel D: g_h = X @ W   fp32 SIMT GEMM  (BM=64 x 128, BK=32)
// ---------------------------------------------------------------------------
#define BM 64
#define BK 32

__global__ __launch_bounds__(256) void gemm_kernel(const float* __restrict__ X,
                                                   const float* __restrict__ W,
                                                   float* __restrict__ H) {
    __shared__ float xs[BM * BK];
    __shared__ float ws[BK * OUT_DIM];

    const int tid = threadIdx.x;
    const int tx  = tid & 31;
    const int ty  = tid >> 5;
    const int row0 = blockIdx.x * BM;

    float acc[8][4];
#pragma unroll
    for (int i = 0; i < 8; i++)
#pragma unroll
        for (int j = 0; j < 4; j++) acc[i][j] = 0.f;

    for (int k0 = 0; k0 < IN_DIM; k0 += BK) {
#pragma unroll
        for (int l = 0; l < 2; l++) {
            int f = tid + l * 256;
            int r  = f >> 3;
            int kc = (f & 7) << 2;
            int grow = row0 + r;
            float4 v = make_float4(0.f, 0.f, 0.f, 0.f);
            if (grow < N_NODES)
                v = *reinterpret_cast<const float4*>(X + (size_t)grow * IN_DIM + k0 + kc);
            *reinterpret_cast<float4*>(xs + r * BK + kc) = v;
        }
#pragma unroll
        for (int l = 0; l < 4; l++) {
            int f = tid + l * 256;
            int kk = f >> 5;
            int c  = (f & 31) << 2;
            *reinterpret_cast<float4*>(ws + kk * OUT_DIM + c) =
                *reinterpret_cast<const float4*>(W + (size_t)(k0 + kk) * OUT_DIM + c);
        }
        __syncthreads();

#pragma unroll
        for (int k = 0; k < BK; k++) {
            float4 wv = *reinterpret_cast<const float4*>(ws + k * OUT_DIM + (tx << 2));
#pragma unroll
            for (int i = 0; i < 8; i++) {
                float xv = xs[(ty * 8 + i) * BK + k];
                acc[i][0] += xv * wv.x;
                acc[i][1] += xv * wv.y;
                acc[i][2] += xv * wv.z;
                acc[i][3] += xv * wv.w;
            }
        }
        __syncthreads();
    }

#pragma unroll
    for (int i = 0; i < 8; i++) {
        int row = row0 + ty * 8 + i;
        if (row < N_NODES) {
            float4 v = make_float4(acc[i][0], acc[i][1], acc[i][2], acc[i][3]);
            *reinterpret_cast<float4*>(H + (size_t)row * OUT_DIM + (tx << 2)) = v;
        }
    }
}

// ---------------------------------------------------------------------------
// Kernel E: gather-reduce. One warp per dst node; no atomics.
// lane l accumulates cols 4l..4l+3 over the node's edge bin; writes acc+bias.
// ---------------------------------------------------------------------------
__global__ __launch_bounds__(256) void gather_kernel(const float* __restrict__ H,
                                                     const float* __restrict__ b,
                                                     float* __restrict__ out) {
    const int warps_per_block = 256 / 32;
    int node = blockIdx.x * warps_per_block + (threadIdx.x >> 5);
    if (node >= N_NODES) return;
    const int lane = threadIdx.x & 31;

    const int beg = g_off[node];
    const int end = g_off[node + 1];

    float4 acc = make_float4(0.f, 0.f, 0.f, 0.f);

    for (int e0 = beg; e0 < end; e0 += 32) {
        // coalesced fetch of up to 32 (src, val) pairs
        int2 ed = make_int2(0, 0);
        if (e0 + lane < end) ed = g_edges[e0 + lane];
        int cnt = min(32, end - e0);

        for (int j = 0; j < cnt; j++) {
            int   s = __shfl_sync(0xFFFFFFFFu, ed.x, j);
            float v = __int_as_float(__shfl_sync(0xFFFFFFFFu, ed.y, j));
            float4 hv = *reinterpret_cast<const float4*>(
                H + (size_t)s * OUT_DIM + (lane << 2));
            acc.x += v * hv.x;
            acc.y += v * hv.y;
            acc.z += v * hv.z;
            acc.w += v * hv.w;
        }
    }

    float4 bv = reinterpret_cast<const float4*>(b)[lane];
    acc.x += bv.x; acc.y += bv.y; acc.z += bv.z; acc.w += bv.w;
    *reinterpret_cast<float4*>(out + (size_t)node * OUT_DIM + (lane << 2)) = acc;
}

// ---------------------------------------------------------------------------
extern "C" void kernel_launch(void* const* d_in, const int* in_sizes, int n_in,
                              void* d_out, int out_size) {
    const float* X    = (const float*)d_in[0];   // [N_NODES, IN_DIM]
    const int*   esrc = (const int*)  d_in[1];   // [N_EDGES]
    const int*   edst = (const int*)  d_in[2];   // [N_EDGES]
    const float* evls = (const float*)d_in[3];   // [N_EDGES]
    const float* W    = (const float*)d_in[4];   // [IN_DIM, OUT_DIM]
    const float* b    = (const float*)d_in[5];   // [OUT_DIM]
    float* out = (float*)d_out;                  // [N_NODES, OUT_DIM]

    float* H = nullptr;
    cudaGetSymbolAddress((void**)&H, g_h);
    int* degp = nullptr; cudaGetSymbolAddress((void**)&degp, g_deg);
    int* curp = nullptr; cudaGetSymbolAddress((void**)&curp, g_cur);

    // zero histogram + cursors (capturable async memsets)
    cudaMemsetAsync(degp, 0, N_NODES * sizeof(int));
    cudaMemsetAsync(curp, 0, N_NODES * sizeof(int));

    // CSR build
    {
        int blocks = (N_EDGES + 255) / 256;
        hist_kernel<<<blocks, 256>>>(edst);
        scan_kernel<<<1, SCAN_THREADS>>>();
        bin_kernel<<<blocks, 256>>>(esrc, edst, evls);
    }

    // H = X @ W
    {
        int blocks = (N_NODES + BM - 1) / BM;
        gemm_kernel<<<blocks, 256>>>(X, W, H);
    }

    // out[n] = sum over bin(n) of val * H[src]  + bias
    {
        int warps_per_block = 256 / 32;
        int blocks = (N_NODES + warps_per_block - 1) / warps_per_block;
        gather_kernel<<<blocks, 256>>>(H, b, out);
    }
}

// round 8
// speedup vs baseline: 2.5346x; 1.0743x over previous
#include <cuda_runtime.h>
#include <cuda_bf16.h>
#include <cstdint>
#include <cstddef>

#define N_NODES 100000
#define IN_DIM  256
#define OUT_DIM 128
#define N_EDGES 3200000

// ---------------------------------------------------------------------------
// Device scratch (static; no allocation allowed)
// ---------------------------------------------------------------------------
__device__ float g_h[(size_t)N_NODES * OUT_DIM];     // 51.2 MB  H = X@W
__device__ int   g_deg[N_NODES];                     // histogram of dst
__device__ int   g_off[N_NODES + 1];                 // CSR row offsets (by dst)
__device__ int   g_cur[N_NODES];                     // scatter cursors
__device__ int2  g_edges[N_EDGES];                   // binned {src, val-bits}

__device__ __forceinline__ uint32_t f2tf32(float x) {
    uint32_t r;
    asm("cvt.rna.tf32.f32 %0, %1;" : "=r"(r) : "f"(x));
    return r;
}

// ---------------------------------------------------------------------------
// GEMM: H[100000,128] = X[100000,256] @ W[256,128] using mma.sync tf32
// (base sm_80+ PTX feature -> compiles at compute_103; HMMA.TF32 tensor pipe)
//
// CTA: 256 thr (8 warps), tile M=128 x N=128, K-chunk 64 single-buffered.
// smem: A[m][k] stride 68, B[n][k] stride 68 (transposed W) -> conflict-free
// fragment loads. Warp grid 4(m) x 2(n); warp tile 32x64 = 2x8 mma tiles.
// ---------------------------------------------------------------------------
#define KC       64
#define NCHUNK   (IN_DIM / KC)         // 4
#define AS_STRIDE 68                   // words
#define BS_STRIDE 68
#define SM_A_WORDS (128 * AS_STRIDE)   // 8704
#define SM_B_WORDS (128 * BS_STRIDE)   // 8704
#define GEMM_SMEM ((SM_A_WORDS + SM_B_WORDS) * 4)   // 69632 B

__device__ __forceinline__ void mma_tf32(float* d, const uint32_t* a, const uint32_t* b) {
    asm volatile(
        "mma.sync.aligned.m16n8k8.row.col.f32.tf32.tf32.f32 "
        "{%0,%1,%2,%3}, {%4,%5,%6,%7}, {%8,%9}, {%0,%1,%2,%3};"
        : "+f"(d[0]), "+f"(d[1]), "+f"(d[2]), "+f"(d[3])
        : "r"(a[0]), "r"(a[1]), "r"(a[2]), "r"(a[3]), "r"(b[0]), "r"(b[1]));
}

__global__ __launch_bounds__(256) void gemm_mma_kernel(const float* __restrict__ X,
                                                       const float* __restrict__ W,
                                                       float* __restrict__ H) {
    extern __shared__ uint32_t smw[];
    uint32_t* sA = smw;                // [128][AS_STRIDE]
    uint32_t* sB = smw + SM_A_WORDS;   // [128][BS_STRIDE]  (B[n][k] = W[k][n])

    const int tid  = threadIdx.x;
    const int wid  = tid >> 5;
    const int lane = tid & 31;
    const int g    = lane >> 2;        // groupID 0..7
    const int tig  = lane & 3;         // thread-in-group 0..3
    const int row0 = blockIdx.x * 128;

    const int m0 = (wid >> 1) * 32;    // warp m offset
    const int n0 = (wid & 1) * 64;     // warp n offset

    float acc[2][8][4];
#pragma unroll
    for (int mt = 0; mt < 2; mt++)
#pragma unroll
        for (int nt = 0; nt < 8; nt++)
#pragma unroll
            for (int q = 0; q < 4; q++) acc[mt][nt][q] = 0.f;

    for (int c = 0; c < NCHUNK; c++) {
        // ---- stage A chunk: 128 rows x KC cols, float4 LDG, uint4 STS
#pragma unroll
        for (int i = 0; i < 8; i++) {
            int f = i * 256 + tid;
            int r = f >> 4;            // row 0..127
            int j = f & 15;            // float4 col
            int grow = row0 + r;
            float4 v = make_float4(0.f, 0.f, 0.f, 0.f);
            if (grow < N_NODES)
                v = *reinterpret_cast<const float4*>(X + (size_t)grow * IN_DIM + c * KC + (j << 2));
            uint4 t;
            t.x = f2tf32(v.x); t.y = f2tf32(v.y); t.z = f2tf32(v.z); t.w = f2tf32(v.w);
            *reinterpret_cast<uint4*>(sA + r * AS_STRIDE + (j << 2)) = t;
        }
        // ---- stage B chunk transposed: sB[n][kl] = W[c*KC+kl][n]
#pragma unroll
        for (int i = 0; i < 32; i++) {
            int f = i * 256 + tid;
            int kl = f >> 7;           // 0..KC-1
            int n  = f & 127;
            sB[n * BS_STRIDE + kl] = f2tf32(__ldg(W + (size_t)(c * KC + kl) * OUT_DIM + n));
        }
        __syncthreads();

        // ---- compute: 8 k-steps of m16n8k8
#pragma unroll 2
        for (int kk = 0; kk < KC / 8; kk++) {
            const int kb = kk * 8;
            uint32_t afr[2][4];
#pragma unroll
            for (int mt = 0; mt < 2; mt++) {
                const uint32_t* ap = sA + (m0 + mt * 16 + g) * AS_STRIDE + kb + tig;
                afr[mt][0] = ap[0];
                afr[mt][1] = ap[8 * AS_STRIDE];
                afr[mt][2] = ap[4];
                afr[mt][3] = ap[8 * AS_STRIDE + 4];
            }
            uint32_t bfr[8][2];
#pragma unroll
            for (int nt = 0; nt < 8; nt++) {
                const uint32_t* bp = sB + (n0 + nt * 8 + g) * BS_STRIDE + kb + tig;
                bfr[nt][0] = bp[0];
                bfr[nt][1] = bp[4];
            }
#pragma unroll
            for (int mt = 0; mt < 2; mt++)
#pragma unroll
                for (int nt = 0; nt < 8; nt++)
                    mma_tf32(acc[mt][nt], afr[mt], bfr[nt]);
        }
        __syncthreads();
    }

    // ---- epilogue: c0,c1 -> float2 at (g, 2tig); c2,c3 at (g+8, 2tig)
#pragma unroll
    for (int mt = 0; mt < 2; mt++) {
        int r_lo = row0 + m0 + mt * 16 + g;
        int r_hi = r_lo + 8;
#pragma unroll
        for (int nt = 0; nt < 8; nt++) {
            int col = n0 + nt * 8 + 2 * tig;
            if (r_lo < N_NODES)
                *reinterpret_cast<float2*>(H + (size_t)r_lo * OUT_DIM + col) =
                    make_float2(acc[mt][nt][0], acc[mt][nt][1]);
            if (r_hi < N_NODES)
                *reinterpret_cast<float2*>(H + (size_t)r_hi * OUT_DIM + col) =
                    make_float2(acc[mt][nt][2], acc[mt][nt][3]);
        }
    }
}

// ---------------------------------------------------------------------------
// Kernel A: histogram of edge destinations
// ---------------------------------------------------------------------------
__global__ __launch_bounds__(256) void hist_kernel(const int* __restrict__ dst) {
    int i = blockIdx.x * blockDim.x + threadIdx.x;
    if (i < N_EDGES) atomicAdd(&g_deg[__ldg(dst + i)], 1);
}

// ---------------------------------------------------------------------------
// Kernel B: exclusive prefix scan g_deg -> g_off (also seeds g_cur)
// ---------------------------------------------------------------------------
#define SCAN_THREADS 1024
#define SCAN_ITEMS   98   // 1024*98 >= N_NODES

__global__ __launch_bounds__(SCAN_THREADS) void scan_kernel() {
    __shared__ int sums[SCAN_THREADS];
    const int t = threadIdx.x;
    const int base = t * SCAN_ITEMS;

    int s = 0;
    for (int i = 0; i < SCAN_ITEMS; i++) {
        int idx = base + i;
        s += (idx < N_NODES) ? g_deg[idx] : 0;
    }
    sums[t] = s;
    __syncthreads();

    for (int ofs = 1; ofs < SCAN_THREADS; ofs <<= 1) {
        int v = (t >= ofs) ? sums[t - ofs] : 0;
        __syncthreads();
        sums[t] += v;
        __syncthreads();
    }
    int prefix = (t == 0) ? 0 : sums[t - 1];

    int run = prefix;
    for (int i = 0; i < SCAN_ITEMS; i++) {
        int idx = base + i;
        if (idx < N_NODES) {
            g_off[idx] = run;
            g_cur[idx] = run;          // cursor seeded with offset
            run += g_deg[idx];
        }
    }
    if (t == SCAN_THREADS - 1) g_off[N_NODES] = sums[SCAN_THREADS - 1];
}

// ---------------------------------------------------------------------------
// Kernel C: scatter edges into dst-sorted bins (cursor holds absolute pos)
// ---------------------------------------------------------------------------
__global__ __launch_bounds__(256) void bin_kernel(const int* __restrict__ src,
                                                  const int* __restrict__ dst,
                                                  const float* __restrict__ vals) {
    int i = blockIdx.x * blockDim.x + threadIdx.x;
    if (i >= N_EDGES) return;
    int d = __ldg(dst + i);
    int pos = atomicAdd(&g_cur[d], 1);
    g_edges[pos] = make_int2(__ldg(src + i), __float_as_int(__ldg(vals + i)));
}

// ---------------------------------------------------------------------------
// Kernel E: gather-reduce. One warp per dst node; no atomics; bias fused.
// ---------------------------------------------------------------------------
__global__ __launch_bounds__(256) void gather_kernel(const float* __restrict__ H,
                                                     const float* __restrict__ b,
                                                     float* __restrict__ out) {
    const int warps_per_block = 256 / 32;
    int node = blockIdx.x * warps_per_block + (threadIdx.x >> 5);
    if (node >= N_NODES) return;
    const int lane = threadIdx.x & 31;

    const int beg = g_off[node];
    const int end = g_off[node + 1];

    float4 acc = make_float4(0.f, 0.f, 0.f, 0.f);

    for (int e0 = beg; e0 < end; e0 += 32) {
        int2 ed = make_int2(0, 0);
        if (e0 + lane < end) ed = g_edges[e0 + lane];
        int cnt = min(32, end - e0);

        for (int j = 0; j < cnt; j++) {
            int   s = __shfl_sync(0xFFFFFFFFu, ed.x, j);
            float v = __int_as_float(__shfl_sync(0xFFFFFFFFu, ed.y, j));
            float4 hv = *reinterpret_cast<const float4*>(
                H + (size_t)s * OUT_DIM + (lane << 2));
            acc.x += v * hv.x;
            acc.y += v * hv.y;
            acc.z += v * hv.z;
            acc.w += v * hv.w;
        }
    }

    float4 bv = reinterpret_cast<const float4*>(b)[lane];
    acc.x += bv.x; acc.y += bv.y; acc.z += bv.z; acc.w += bv.w;
    *reinterpret_cast<float4*>(out + (size_t)node * OUT_DIM + (lane << 2)) = acc;
}

// ---------------------------------------------------------------------------
extern "C" void kernel_launch(void* const* d_in, const int* in_sizes, int n_in,
                              void* d_out, int out_size) {
    const float* X    = (const float*)d_in[0];   // [N_NODES, IN_DIM]
    const int*   esrc = (const int*)  d_in[1];   // [N_EDGES]
    const int*   edst = (const int*)  d_in[2];   // [N_EDGES]
    const float* evls = (const float*)d_in[3];   // [N_EDGES]
    const float* W    = (const float*)d_in[4];   // [IN_DIM, OUT_DIM]
    const float* b    = (const float*)d_in[5];   // [OUT_DIM]
    float* out = (float*)d_out;                  // [N_NODES, OUT_DIM]

    float* H = nullptr;
    cudaGetSymbolAddress((void**)&H, g_h);
    int* degp = nullptr; cudaGetSymbolAddress((void**)&degp, g_deg);

    cudaMemsetAsync(degp, 0, N_NODES * sizeof(int));

    // CSR build
    {
        int blocks = (N_EDGES + 255) / 256;
        hist_kernel<<<blocks, 256>>>(edst);
        scan_kernel<<<1, SCAN_THREADS>>>();
        bin_kernel<<<blocks, 256>>>(esrc, edst, evls);
    }

    // H = X @ W  (tf32 mma.sync tensor path)
    {
        cudaFuncSetAttribute(gemm_mma_kernel,
                             cudaFuncAttributeMaxDynamicSharedMemorySize, GEMM_SMEM);
        int blocks = (N_NODES + 127) / 128;      // 782
        gemm_mma_kernel<<<blocks, 256, GEMM_SMEM>>>(X, W, H);
    }

    // out[n] = sum over bin(n) of val * H[src]  + bias
    {
        int warps_per_block = 256 / 32;
        int blocks = (N_NODES + warps_per_block - 1) / warps_per_block;
        gather_kernel<<<blocks, 256>>>(H, b, out);
    }
}

// round 9
// speedup vs baseline: 3.6670x; 1.4468x over previous
#include <cuda_runtime.h>
#include <cuda_bf16.h>
#include <cuda_fp16.h>
#include <cstdint>
#include <cstddef>

#define N_NODES 100000
#define IN_DIM  256
#define OUT_DIM 128
#define N_EDGES 3200000

// ---------------------------------------------------------------------------
// Device scratch (static; no allocation allowed)
// ---------------------------------------------------------------------------
__device__ __align__(16) __half g_h[(size_t)N_NODES * OUT_DIM];  // 25.6 MB H (fp16)
__device__ __align__(16) int    g_deg[N_NODES];
__device__ __align__(16) int    g_off[N_NODES + 1];
__device__ __align__(16) int    g_cur[N_NODES];
__device__ int2                 g_edges[N_EDGES];

__device__ __forceinline__ uint32_t f2tf32(float x) {
    uint32_t r;
    asm("cvt.rna.tf32.f32 %0, %1;" : "=r"(r) : "f"(x));
    return r;
}
__device__ __forceinline__ uint32_t smem_u32(const void* p) {
    uint32_t a;
    asm("{ .reg .u64 t; cvta.to.shared.u64 t, %1; cvt.u32.u64 %0, t; }" : "=r"(a) : "l"(p));
    return a;
}
__device__ __forceinline__ void cp_async16(uint32_t s_addr, const void* g_ptr, uint32_t src_sz) {
    asm volatile("cp.async.ca.shared.global [%0], [%1], 16, %2;"
                 :: "r"(s_addr), "l"(g_ptr), "r"(src_sz) : "memory");
}
#define CP_COMMIT() asm volatile("cp.async.commit_group;" ::: "memory")
#define CP_WAIT(n)  asm volatile("cp.async.wait_group %0;" :: "n"(n) : "memory")

// ---------------------------------------------------------------------------
// GEMM: H[100000,128] = X[100000,256] @ W[256,128], tf32 mma.sync.
// W staged ONCE transposed+tf32 in smem [n][k] stride 260 (133 KB).
// A double-buffered raw fp32 via cp.async (2 x 34.8 KB), cvt at fragment load.
// CTA 256 thr, tile 128x128; warp grid 4x2, warp tile 32x64 (2x8 m16n8k8).
// ---------------------------------------------------------------------------
#define KC        64
#define NCHUNK    (IN_DIM / KC)          // 4
#define AS_STRIDE 68                     // words
#define BW_STRIDE 260                    // words (256 + 4 pad)
#define SM_A_WORDS (128 * AS_STRIDE)     // 8704 per stage
#define SM_B_WORDS (128 * BW_STRIDE)     // 33280
#define GEMM_SMEM ((2 * SM_A_WORDS + SM_B_WORDS) * 4)   // 202752 B

__device__ __forceinline__ void mma_tf32(float* d, const uint32_t* a, const uint32_t* b) {
    asm volatile(
        "mma.sync.aligned.m16n8k8.row.col.f32.tf32.tf32.f32 "
        "{%0,%1,%2,%3}, {%4,%5,%6,%7}, {%8,%9}, {%0,%1,%2,%3};"
        : "+f"(d[0]), "+f"(d[1]), "+f"(d[2]), "+f"(d[3])
        : "r"(a[0]), "r"(a[1]), "r"(a[2]), "r"(a[3]), "r"(b[0]), "r"(b[1]));
}

__global__ __launch_bounds__(256) void gemm_mma_kernel(const float* __restrict__ X,
                                                       const float* __restrict__ W,
                                                       __half* __restrict__ H) {
    extern __shared__ uint32_t smw[];
    uint32_t* sB = smw;                      // [128][BW_STRIDE] tf32 (W transposed)
    uint32_t* sA = smw + SM_B_WORDS;         // [2][128][AS_STRIDE] raw fp32

    const int tid  = threadIdx.x;
    const int wid  = tid >> 5;
    const int lane = tid & 31;
    const int g    = lane >> 2;
    const int tig  = lane & 3;
    const int row0 = blockIdx.x * 128;

    const int m0 = (wid >> 1) * 32;
    const int n0 = (wid & 1) * 64;

    // ---- issue A chunk 0 (async), then stage B while it flies
    {
        uint32_t s_base = smem_u32(sA);
#pragma unroll
        for (int i = 0; i < 8; i++) {
            int f = i * 256 + tid;
            int r = f >> 4, j = f & 15;
            int grow = row0 + r;
            const float* gp = X + (size_t)min(grow, N_NODES - 1) * IN_DIM + (j << 2);
            cp_async16(s_base + (r * AS_STRIDE + (j << 2)) * 4, gp,
                       (grow < N_NODES) ? 16u : 0u);
        }
        CP_COMMIT();
    }
    // stage full W transposed: sB[n][k] = tf32(W[k][n]); 128 loads/thread
#pragma unroll
    for (int i = 0; i < 128; i++) {
        int f = i * 256 + tid;
        int kl = f >> 7;               // 0..255
        int n  = f & 127;
        sB[n * BW_STRIDE + kl] = f2tf32(__ldg(W + (size_t)kl * OUT_DIM + n));
    }

    float acc[2][8][4];
#pragma unroll
    for (int mt = 0; mt < 2; mt++)
#pragma unroll
        for (int nt = 0; nt < 8; nt++)
#pragma unroll
            for (int q = 0; q < 4; q++) acc[mt][nt][q] = 0.f;

    for (int c = 0; c < NCHUNK; c++) {
        // issue next A chunk into other buffer
        if (c + 1 < NCHUNK) {
            uint32_t s_base = smem_u32(sA + ((c + 1) & 1) * SM_A_WORDS);
#pragma unroll
            for (int i = 0; i < 8; i++) {
                int f = i * 256 + tid;
                int r = f >> 4, j = f & 15;
                int grow = row0 + r;
                const float* gp = X + (size_t)min(grow, N_NODES - 1) * IN_DIM
                                  + (c + 1) * KC + (j << 2);
                cp_async16(s_base + (r * AS_STRIDE + (j << 2)) * 4, gp,
                           (grow < N_NODES) ? 16u : 0u);
            }
            CP_COMMIT();
            CP_WAIT(1);                 // chunk c arrived
        } else {
            CP_WAIT(0);
        }
        __syncthreads();

        const uint32_t* sAc = sA + (c & 1) * SM_A_WORDS;
        const int kw = c * KC;          // k offset into sB

#pragma unroll 2
        for (int kk = 0; kk < KC / 8; kk++) {
            const int kb = kk * 8;
            uint32_t afr[2][4];
#pragma unroll
            for (int mt = 0; mt < 2; mt++) {
                const uint32_t* ap = sAc + (m0 + mt * 16 + g) * AS_STRIDE + kb + tig;
                afr[mt][0] = f2tf32(__uint_as_float(ap[0]));
                afr[mt][1] = f2tf32(__uint_as_float(ap[8 * AS_STRIDE]));
                afr[mt][2] = f2tf32(__uint_as_float(ap[4]));
                afr[mt][3] = f2tf32(__uint_as_float(ap[8 * AS_STRIDE + 4]));
            }
            uint32_t bfr[8][2];
#pragma unroll
            for (int nt = 0; nt < 8; nt++) {
                const uint32_t* bp = sB + (n0 + nt * 8 + g) * BW_STRIDE + kw + kb + tig;
                bfr[nt][0] = bp[0];
                bfr[nt][1] = bp[4];
            }
#pragma unroll
            for (int mt = 0; mt < 2; mt++)
#pragma unroll
                for (int nt = 0; nt < 8; nt++)
                    mma_tf32(acc[mt][nt], afr[mt], bfr[nt]);
        }
        __syncthreads();
    }

    // ---- epilogue: fp16 stores
#pragma unroll
    for (int mt = 0; mt < 2; mt++) {
        int r_lo = row0 + m0 + mt * 16 + g;
        int r_hi = r_lo + 8;
#pragma unroll
        for (int nt = 0; nt < 8; nt++) {
            int col = n0 + nt * 8 + 2 * tig;
            if (r_lo < N_NODES)
                *reinterpret_cast<__half2*>(H + (size_t)r_lo * OUT_DIM + col) =
                    __floats2half2_rn(acc[mt][nt][0], acc[mt][nt][1]);
            if (r_hi < N_NODES)
                *reinterpret_cast<__half2*>(H + (size_t)r_hi * OUT_DIM + col) =
                    __floats2half2_rn(acc[mt][nt][2], acc[mt][nt][3]);
        }
    }
}

// ---------------------------------------------------------------------------
// Kernel A: histogram of edge destinations
// ---------------------------------------------------------------------------
__global__ __launch_bounds__(256) void hist_kernel(const int* __restrict__ dst) {
    int i = blockIdx.x * blockDim.x + threadIdx.x;
    if (i < N_EDGES) atomicAdd(&g_deg[__ldg(dst + i)], 1);
}

// ---------------------------------------------------------------------------
// Kernel B: vectorized exclusive scan g_deg -> g_off (+ seeds g_cur)
// 1024 threads, 100 items/thread (int4 x 25); threads >= 1000 idle.
// ---------------------------------------------------------------------------
#define SCAN_THREADS 1024
#define SCAN_ITEMS   100

__global__ __launch_bounds__(SCAN_THREADS) void scan_kernel() {
    __shared__ int sums[SCAN_THREADS];
    const int t = threadIdx.x;
    const int base = t * SCAN_ITEMS;
    const bool live = (base < N_NODES);   // threads 0..999

    int s = 0;
    if (live) {
        const int4* dp = reinterpret_cast<const int4*>(g_deg + base);
#pragma unroll
        for (int i = 0; i < SCAN_ITEMS / 4; i++) {
            int4 v = dp[i];
            s += v.x + v.y + v.z + v.w;
        }
    }
    sums[t] = s;
    __syncthreads();

    for (int ofs = 1; ofs < SCAN_THREADS; ofs <<= 1) {
        int v = (t >= ofs) ? sums[t - ofs] : 0;
        __syncthreads();
        sums[t] += v;
        __syncthreads();
    }
    int run = (t == 0) ? 0 : sums[t - 1];

    if (live) {
        const int4* dp = reinterpret_cast<const int4*>(g_deg + base);
        int4* op = reinterpret_cast<int4*>(g_off + base);
        int4* cp = reinterpret_cast<int4*>(g_cur + base);
#pragma unroll
        for (int i = 0; i < SCAN_ITEMS / 4; i++) {
            int4 v = dp[i];
            int4 o;
            o.x = run;
            o.y = o.x + v.x;
            o.z = o.y + v.y;
            o.w = o.z + v.z;
            run = o.w + v.w;
            op[i] = o;
            cp[i] = o;
        }
    }
    if (t == 0) g_off[N_NODES] = sums[SCAN_THREADS - 1];
}

// ---------------------------------------------------------------------------
// Kernel C: scatter edges into dst-sorted bins
// ---------------------------------------------------------------------------
__global__ __launch_bounds__(256) void bin_kernel(const int* __restrict__ src,
                                                  const int* __restrict__ dst,
                                                  const float* __restrict__ vals) {
    int i = blockIdx.x * blockDim.x + threadIdx.x;
    if (i >= N_EDGES) return;
    int d = __ldg(dst + i);
    int pos = atomicAdd(&g_cur[d], 1);
    g_edges[pos] = make_int2(__ldg(src + i), __float_as_int(__ldg(vals + i)));
}

// ---------------------------------------------------------------------------
// Kernel E: gather-reduce over fp16 H. One warp per dst node; bias fused.
// lane l: cols 4l..4l+3 (8 B of fp16 per lane -> warp covers the 256 B row).
// ---------------------------------------------------------------------------
__global__ __launch_bounds__(256) void gather_kernel(const __half* __restrict__ H,
                                                     const float* __restrict__ b,
                                                     float* __restrict__ out) {
    const int warps_per_block = 256 / 32;
    int node = blockIdx.x * warps_per_block + (threadIdx.x >> 5);
    if (node >= N_NODES) return;
    const int lane = threadIdx.x & 31;

    const int beg = g_off[node];
    const int end = g_off[node + 1];

    float4 acc = make_float4(0.f, 0.f, 0.f, 0.f);

    for (int e0 = beg; e0 < end; e0 += 32) {
        int2 ed = make_int2(0, 0);
        if (e0 + lane < end) ed = g_edges[e0 + lane];
        int cnt = min(32, end - e0);

        for (int j = 0; j < cnt; j++) {
            int   s = __shfl_sync(0xFFFFFFFFu, ed.x, j);
            float v = __int_as_float(__shfl_sync(0xFFFFFFFFu, ed.y, j));
            uint2 u = *reinterpret_cast<const uint2*>(
                H + (size_t)s * OUT_DIM + (lane << 2));
            float2 h01 = __half22float2(*reinterpret_cast<__half2*>(&u.x));
            float2 h23 = __half22float2(*reinterpret_cast<__half2*>(&u.y));
            acc.x += v * h01.x;
            acc.y += v * h01.y;
            acc.z += v * h23.x;
            acc.w += v * h23.y;
        }
    }

    float4 bv = reinterpret_cast<const float4*>(b)[lane];
    acc.x += bv.x; acc.y += bv.y; acc.z += bv.z; acc.w += bv.w;
    *reinterpret_cast<float4*>(out + (size_t)node * OUT_DIM + (lane << 2)) = acc;
}

// ---------------------------------------------------------------------------
extern "C" void kernel_launch(void* const* d_in, const int* in_sizes, int n_in,
                              void* d_out, int out_size) {
    const float* X    = (const float*)d_in[0];
    const int*   esrc = (const int*)  d_in[1];
    const int*   edst = (const int*)  d_in[2];
    const float* evls = (const float*)d_in[3];
    const float* W    = (const float*)d_in[4];
    const float* b    = (const float*)d_in[5];
    float* out = (float*)d_out;

    __half* H = nullptr;
    cudaGetSymbolAddress((void**)&H, g_h);
    int* degp = nullptr; cudaGetSymbolAddress((void**)&degp, g_deg);

    cudaMemsetAsync(degp, 0, N_NODES * sizeof(int));

    // CSR build
    {
        int blocks = (N_EDGES + 255) / 256;
        hist_kernel<<<blocks, 256>>>(edst);
        scan_kernel<<<1, SCAN_THREADS>>>();
        bin_kernel<<<blocks, 256>>>(esrc, edst, evls);
    }

    // H = X @ W  (tf32 mma.sync, cp.async pipelined, fp16 out)
    {
        cudaFuncSetAttribute(gemm_mma_kernel,
                             cudaFuncAttributeMaxDynamicSharedMemorySize, GEMM_SMEM);
        int blocks = (N_NODES + 127) / 128;      // 782
        gemm_mma_kernel<<<blocks, 256, GEMM_SMEM>>>(X, W, H);
    }

    // out[n] = sum over bin(n) of val * H[src]  + bias
    {
        int warps_per_block = 256 / 32;
        int blocks = (N_NODES + warps_per_block - 1) / warps_per_block;
        gather_kernel<<<blocks, 256>>>(H, b, out);
    }
}

// round 10
// speedup vs baseline: 4.0746x; 1.1111x over previous
#include <cuda_runtime.h>
#include <cuda_bf16.h>
#include <cuda_fp16.h>
#include <cstdint>
#include <cstddef>

#define N_NODES 100000
#define IN_DIM  256
#define OUT_DIM 128
#define N_EDGES 3200000

// ---------------------------------------------------------------------------
// Device scratch (static; no allocation allowed)
// ---------------------------------------------------------------------------
__device__ __align__(16) __half g_h[(size_t)N_NODES * OUT_DIM];  // 25.6 MB H (fp16)
__device__ __align__(16) int    g_deg[N_NODES];
__device__ __align__(16) int    g_off[N_NODES + 1];
__device__ __align__(16) int    g_cur[N_NODES];
__device__ int2                 g_edges[N_EDGES];

__device__ __forceinline__ uint32_t f2tf32(float x) {
    uint32_t r;
    asm("cvt.rna.tf32.f32 %0, %1;" : "=r"(r) : "f"(x));
    return r;
}
__device__ __forceinline__ uint32_t smem_u32(const void* p) {
    uint32_t a;
    asm("{ .reg .u64 t; cvta.to.shared.u64 t, %1; cvt.u32.u64 %0, t; }" : "=r"(a) : "l"(p));
    return a;
}
__device__ __forceinline__ void cp_async16(uint32_t s_addr, const void* g_ptr, uint32_t src_sz) {
    asm volatile("cp.async.ca.shared.global [%0], [%1], 16, %2;"
                 :: "r"(s_addr), "l"(g_ptr), "r"(src_sz) : "memory");
}
#define CP_COMMIT() asm volatile("cp.async.commit_group;" ::: "memory")
#define CP_WAIT(n)  asm volatile("cp.async.wait_group %0;" :: "n"(n) : "memory")

// ---------------------------------------------------------------------------
// GEMM: H[100000,128] = X[100000,256] @ W[256,128], tf32 mma.sync.
// KC=32, BOTH A and B double-buffered. smem 73.7 KB -> 2 CTAs/SM (reg-bound).
// A: cp.async raw fp32, cvt at fragment load. B: coalesced ldg + STS (tf32).
// CTA 256 thr, tile 128x128; warp grid 4x2, warp tile 32x64 (2x8 m16n8k8).
// ---------------------------------------------------------------------------
#define KC        32
#define NCHUNK    (IN_DIM / KC)          // 8
#define AS_STRIDE 36                     // words (32 + 4 pad): 36 mod 32 = 4
#define BS_STRIDE 36
#define SM_A_WORDS (128 * AS_STRIDE)     // 4608 per stage
#define SM_B_WORDS (128 * BS_STRIDE)     // 4608 per stage
#define GEMM_SMEM ((2 * SM_A_WORDS + 2 * SM_B_WORDS) * 4)   // 73728 B

__device__ __forceinline__ void mma_tf32(float* d, const uint32_t* a, const uint32_t* b) {
    asm volatile(
        "mma.sync.aligned.m16n8k8.row.col.f32.tf32.tf32.f32 "
        "{%0,%1,%2,%3}, {%4,%5,%6,%7}, {%8,%9}, {%0,%1,%2,%3};"
        : "+f"(d[0]), "+f"(d[1]), "+f"(d[2]), "+f"(d[3])
        : "r"(a[0]), "r"(a[1]), "r"(a[2]), "r"(a[3]), "r"(b[0]), "r"(b[1]));
}

__device__ __forceinline__ void stage_A(uint32_t s_base, const float* __restrict__ X,
                                        int row0, int c, int tid) {
    // 128 rows x 8 float4; 4 float4 per thread
#pragma unroll
    for (int i = 0; i < 4; i++) {
        int f = i * 256 + tid;
        int r = f >> 3, j = f & 7;
        int grow = row0 + r;
        const float* gp = X + (size_t)min(grow, N_NODES - 1) * IN_DIM + c * KC + (j << 2);
        cp_async16(s_base + (r * AS_STRIDE + (j << 2)) * 4, gp,
                   (grow < N_NODES) ? 16u : 0u);
    }
}

__device__ __forceinline__ void stage_B(uint32_t* sBs, const float* __restrict__ W,
                                        int c, int tid) {
    // sB[n][kl] = tf32(W[c*KC+kl][n]); 16 words per thread, coalesced ldg
#pragma unroll
    for (int i = 0; i < 16; i++) {
        int f = i * 256 + tid;
        int n  = f & 127;
        int kl = f >> 7;               // 0..31
        sBs[n * BS_STRIDE + kl] = f2tf32(__ldg(W + (size_t)(c * KC + kl) * OUT_DIM + n));
    }
}

__global__ __launch_bounds__(256) void gemm_mma_kernel(const float* __restrict__ X,
                                                       const float* __restrict__ W,
                                                       __half* __restrict__ H) {
    extern __shared__ uint32_t smw[];
    uint32_t* sA = smw;                          // [2][128][AS_STRIDE] raw fp32
    uint32_t* sB = smw + 2 * SM_A_WORDS;         // [2][128][BS_STRIDE] tf32

    const int tid  = threadIdx.x;
    const int wid  = tid >> 5;
    const int lane = tid & 31;
    const int g    = lane >> 2;
    const int tig  = lane & 3;
    const int row0 = blockIdx.x * 128;

    const int m0 = (wid >> 1) * 32;
    const int n0 = (wid & 1) * 64;

    uint32_t sA_addr = smem_u32(sA);

    // prologue: stage chunk 0
    stage_A(sA_addr, X, row0, 0, tid);
    CP_COMMIT();
    stage_B(sB, W, 0, tid);

    float acc[2][8][4];
#pragma unroll
    for (int mt = 0; mt < 2; mt++)
#pragma unroll
        for (int nt = 0; nt < 8; nt++)
#pragma unroll
            for (int q = 0; q < 4; q++) acc[mt][nt][q] = 0.f;

    for (int c = 0; c < NCHUNK; c++) {
        if (c + 1 < NCHUNK) {
            stage_A(sA_addr + ((c + 1) & 1) * SM_A_WORDS * 4, X, row0, c + 1, tid);
            CP_COMMIT();
            stage_B(sB + ((c + 1) & 1) * SM_B_WORDS, W, c + 1, tid);
            CP_WAIT(1);                 // chunk c A arrived
        } else {
            CP_WAIT(0);
        }
        __syncthreads();                // A(c)+B(c) visible to all

        const uint32_t* sAc = sA + (c & 1) * SM_A_WORDS;
        const uint32_t* sBc = sB + (c & 1) * SM_B_WORDS;

#pragma unroll
        for (int kk = 0; kk < KC / 8; kk++) {
            const int kb = kk * 8;
            uint32_t afr[2][4];
#pragma unroll
            for (int mt = 0; mt < 2; mt++) {
                const uint32_t* ap = sAc + (m0 + mt * 16 + g) * AS_STRIDE + kb + tig;
                afr[mt][0] = f2tf32(__uint_as_float(ap[0]));
                afr[mt][1] = f2tf32(__uint_as_float(ap[8 * AS_STRIDE]));
                afr[mt][2] = f2tf32(__uint_as_float(ap[4]));
                afr[mt][3] = f2tf32(__uint_as_float(ap[8 * AS_STRIDE + 4]));
            }
            uint32_t bfr[8][2];
#pragma unroll
            for (int nt = 0; nt < 8; nt++) {
                const uint32_t* bp = sBc + (n0 + nt * 8 + g) * BS_STRIDE + kb + tig;
                bfr[nt][0] = bp[0];
                bfr[nt][1] = bp[4];
            }
#pragma unroll
            for (int mt = 0; mt < 2; mt++)
#pragma unroll
                for (int nt = 0; nt < 8; nt++)
                    mma_tf32(acc[mt][nt], afr[mt], bfr[nt]);
        }
        __syncthreads();                // protect buffers before next staging
    }

    // ---- epilogue: fp16 stores
#pragma unroll
    for (int mt = 0; mt < 2; mt++) {
        int r_lo = row0 + m0 + mt * 16 + g;
        int r_hi = r_lo + 8;
#pragma unroll
        for (int nt = 0; nt < 8; nt++) {
            int col = n0 + nt * 8 + 2 * tig;
            if (r_lo < N_NODES)
                *reinterpret_cast<__half2*>(H + (size_t)r_lo * OUT_DIM + col) =
                    __floats2half2_rn(acc[mt][nt][0], acc[mt][nt][1]);
            if (r_hi < N_NODES)
                *reinterpret_cast<__half2*>(H + (size_t)r_hi * OUT_DIM + col) =
                    __floats2half2_rn(acc[mt][nt][2], acc[mt][nt][3]);
        }
    }
}

// ---------------------------------------------------------------------------
// Kernel A: histogram of edge destinations (2 edges/thread)
// ---------------------------------------------------------------------------
__global__ __launch_bounds__(256) void hist_kernel(const int* __restrict__ dst) {
    int i = blockIdx.x * blockDim.x + threadIdx.x;
    if (2 * i + 1 < N_EDGES) {
        int2 d = *reinterpret_cast<const int2*>(dst + 2 * i);
        atomicAdd(&g_deg[d.x], 1);
        atomicAdd(&g_deg[d.y], 1);
    } else if (2 * i < N_EDGES) {
        atomicAdd(&g_deg[__ldg(dst + 2 * i)], 1);
    }
}

// ---------------------------------------------------------------------------
// Kernel B: vectorized exclusive scan g_deg -> g_off (+ seeds g_cur)
// ---------------------------------------------------------------------------
#define SCAN_THREADS 1024
#define SCAN_ITEMS   100

__global__ __launch_bounds__(SCAN_THREADS) void scan_kernel() {
    __shared__ int sums[SCAN_THREADS];
    const int t = threadIdx.x;
    const int base = t * SCAN_ITEMS;
    const bool live = (base < N_NODES);

    int s = 0;
    if (live) {
        const int4* dp = reinterpret_cast<const int4*>(g_deg + base);
#pragma unroll
        for (int i = 0; i < SCAN_ITEMS / 4; i++) {
            int4 v = dp[i];
            s += v.x + v.y + v.z + v.w;
        }
    }
    sums[t] = s;
    __syncthreads();

    for (int ofs = 1; ofs < SCAN_THREADS; ofs <<= 1) {
        int v = (t >= ofs) ? sums[t - ofs] : 0;
        __syncthreads();
        sums[t] += v;
        __syncthreads();
    }
    int run = (t == 0) ? 0 : sums[t - 1];

    if (live) {
        const int4* dp = reinterpret_cast<const int4*>(g_deg + base);
        int4* op = reinterpret_cast<int4*>(g_off + base);
        int4* cp = reinterpret_cast<int4*>(g_cur + base);
#pragma unroll
        for (int i = 0; i < SCAN_ITEMS / 4; i++) {
            int4 v = dp[i];
            int4 o;
            o.x = run;
            o.y = o.x + v.x;
            o.z = o.y + v.y;
            o.w = o.z + v.z;
            run = o.w + v.w;
            op[i] = o;
            cp[i] = o;
        }
    }
    if (t == 0) g_off[N_NODES] = sums[SCAN_THREADS - 1];
}

// ---------------------------------------------------------------------------
// Kernel C: scatter edges into dst-sorted bins (2 edges/thread)
// ---------------------------------------------------------------------------
__global__ __launch_bounds__(256) void bin_kernel(const int* __restrict__ src,
                                                  const int* __restrict__ dst,
                                                  const float* __restrict__ vals) {
    int i = blockIdx.x * blockDim.x + threadIdx.x;
    int e0 = 2 * i;
    if (e0 + 1 < N_EDGES) {
        int2   s = *reinterpret_cast<const int2*>(src + e0);
        int2   d = *reinterpret_cast<const int2*>(dst + e0);
        float2 v = *reinterpret_cast<const float2*>(vals + e0);
        int p0 = atomicAdd(&g_cur[d.x], 1);
        int p1 = atomicAdd(&g_cur[d.y], 1);
        g_edges[p0] = make_int2(s.x, __float_as_int(v.x));
        g_edges[p1] = make_int2(s.y, __float_as_int(v.y));
    } else if (e0 < N_EDGES) {
        int d = __ldg(dst + e0);
        int p = atomicAdd(&g_cur[d], 1);
        g_edges[p] = make_int2(__ldg(src + e0), __float_as_int(__ldg(vals + e0)));
    }
}

// ---------------------------------------------------------------------------
// Kernel E: gather-reduce over fp16 H. One warp per dst node; bias fused.
// Full 32-edge groups take an unrolled loop (software-pipelined LDGs).
// ---------------------------------------------------------------------------
__global__ __launch_bounds__(256) void gather_kernel(const __half* __restrict__ H,
                                                     const float* __restrict__ b,
                                                     float* __restrict__ out) {
    const int warps_per_block = 256 / 32;
    int node = blockIdx.x * warps_per_block + (threadIdx.x >> 5);
    if (node >= N_NODES) return;
    const int lane = threadIdx.x & 31;

    const int beg = g_off[node];
    const int end = g_off[node + 1];

    float4 acc = make_float4(0.f, 0.f, 0.f, 0.f);
    int e0 = beg;

    // full groups of 32: constant trip count -> unrolled, loads pipelined
    for (; e0 + 32 <= end; e0 += 32) {
        int2 ed = g_edges[e0 + lane];
#pragma unroll
        for (int j = 0; j < 32; j++) {
            int   s = __shfl_sync(0xFFFFFFFFu, ed.x, j);
            float v = __int_as_float(__shfl_sync(0xFFFFFFFFu, ed.y, j));
            uint2 u = *reinterpret_cast<const uint2*>(
                H + (size_t)s * OUT_DIM + (lane << 2));
            float2 h01 = __half22float2(*reinterpret_cast<__half2*>(&u.x));
            float2 h23 = __half22float2(*reinterpret_cast<__half2*>(&u.y));
            acc.x += v * h01.x;
            acc.y += v * h01.y;
            acc.z += v * h23.x;
            acc.w += v * h23.y;
        }
    }
    // remainder
    if (e0 < end) {
        int2 ed = make_int2(0, 0);
        if (e0 + lane < end) ed = g_edges[e0 + lane];
        int cnt = end - e0;
        for (int j = 0; j < cnt; j++) {
            int   s = __shfl_sync(0xFFFFFFFFu, ed.x, j);
            float v = __int_as_float(__shfl_sync(0xFFFFFFFFu, ed.y, j));
            uint2 u = *reinterpret_cast<const uint2*>(
                H + (size_t)s * OUT_DIM + (lane << 2));
            float2 h01 = __half22float2(*reinterpret_cast<__half2*>(&u.x));
            float2 h23 = __half22float2(*reinterpret_cast<__half2*>(&u.y));
            acc.x += v * h01.x;
            acc.y += v * h01.y;
            acc.z += v * h23.x;
            acc.w += v * h23.y;
        }
    }

    float4 bv = reinterpret_cast<const float4*>(b)[lane];
    acc.x += bv.x; acc.y += bv.y; acc.z += bv.z; acc.w += bv.w;
    *reinterpret_cast<float4*>(out + (size_t)node * OUT_DIM + (lane << 2)) = acc;
}

// ---------------------------------------------------------------------------
extern "C" void kernel_launch(void* const* d_in, const int* in_sizes, int n_in,
                              void* d_out, int out_size) {
    const float* X    = (const float*)d_in[0];
    const int*   esrc = (const int*)  d_in[1];
    const int*   edst = (const int*)  d_in[2];
    const float* evls = (const float*)d_in[3];
    const float* W    = (const float*)d_in[4];
    const float* b    = (const float*)d_in[5];
    float* out = (float*)d_out;

    __half* H = nullptr;
    cudaGetSymbolAddress((void**)&H, g_h);
    int* degp = nullptr; cudaGetSymbolAddress((void**)&degp, g_deg);

    cudaMemsetAsync(degp, 0, N_NODES * sizeof(int));

    // CSR build
    {
        int blocks2 = (N_EDGES / 2 + 255) / 256;
        hist_kernel<<<blocks2, 256>>>(edst);
        scan_kernel<<<1, SCAN_THREADS>>>();
        bin_kernel<<<blocks2, 256>>>(esrc, edst, evls);
    }

    // H = X @ W  (tf32 mma.sync, dual double-buffer, fp16 out)
    {
        cudaFuncSetAttribute(gemm_mma_kernel,
                             cudaFuncAttributeMaxDynamicSharedMemorySize, GEMM_SMEM);
        int blocks = (N_NODES + 127) / 128;      // 782
        gemm_mma_kernel<<<blocks, 256, GEMM_SMEM>>>(X, W, H);
    }

    // out[n] = sum over bin(n) of val * H[src]  + bias
    {
        int warps_per_block = 256 / 32;
        int blocks = (N_NODES + warps_per_block - 1) / warps_per_block;
        gather_kernel<<<blocks, 256>>>(H, b, out);
    }
}